// round 8
// baseline (speedup 1.0000x reference)
#include <cuda_runtime.h>
#include <cstdint>

#define NN        8192
#define KSEL      64
#define NTHREADS  256
#define RPB       4              // rows per block (software pipeline depth)
#define WCAP      64             // per-warp candidate slots
#define FCAP      (8 * WCAP)     // fallback candidate cap (512)
#define DCAP      256            // dense candidate cap for fast path
#define THRESH    2.3f

__device__ __forceinline__ uint64_t make_key(uint32_t bits, uint32_t idx) {
    // larger key == larger value; ties -> smaller index (top_k order)
    return ((uint64_t)bits << 16) | (uint64_t)(0xFFFFu ^ idx);
}

// Warp-aggregated histogram add (fallback path only).
__device__ __forceinline__ void hist_add(uint32_t* hist, uint32_t bin, bool pred, int lane) {
    unsigned act = __ballot_sync(0xffffffffu, pred);
    if (pred) {
        unsigned same   = __match_any_sync(act, bin);
        int      leader = __ffs(same) - 1;
        if (lane == leader) atomicAdd(&hist[bin], (uint32_t)__popc(same));
    }
}

__global__ __launch_bounds__(NTHREADS, 4)
void topk_mask_kernel(const float* __restrict__ A, float* __restrict__ out)
{
    __shared__ float4   zbuf[256];            // 4KB zero tile for bulk stores
    __shared__ uint64_t seg[2][FCAP];         // double-buffered per-warp segments
    __shared__ uint64_t dcand[DCAP];
    __shared__ uint32_t cnt_s[2][8];
    __shared__ uint32_t hist[256];            // fallback only
    __shared__ uint32_t wsum[8];
    __shared__ uint32_t fb_count, sh_b, sh_kp, sh_deg;

    const int    tid  = threadIdx.x;
    const int    lane = tid & 31;
    const int    warp = tid >> 5;
    const size_t row0 = (size_t)blockIdx.x * RPB;
    const unsigned ltm = (1u << lane) - 1u;

    zbuf[tid] = make_float4(0.0f, 0.0f, 0.0f, 0.0f);
    __syncthreads();

    // Prologue: async zero-fill for row 0, then loads for row 0 (MLP=8).
    if (tid == 0) {
        asm volatile("fence.proxy.async.shared::cta;" ::: "memory");
        uint32_t zaddr = (uint32_t)__cvta_generic_to_shared(zbuf);
        float* o0 = out + row0 * (size_t)NN;
        #pragma unroll
        for (int k = 0; k < 8; ++k)
            asm volatile("cp.async.bulk.global.shared::cta.bulk_group [%0], [%1], %2;"
                         :: "l"(o0 + k * 1024), "r"(zaddr), "r"(4096) : "memory");
        asm volatile("cp.async.bulk.commit_group;" ::: "memory");
    }

    float4 v[8];
    {
        const float4* ar = reinterpret_cast<const float4*>(A + row0 * (size_t)NN);
        #pragma unroll
        for (int u = 0; u < 8; ++u) v[u] = ar[tid + u * NTHREADS];
    }

    for (int r = 0; r < RPB; ++r) {
        const int p = r & 1;
        const size_t row = row0 + r;
        float* orowf = out + row * (size_t)NN;

        // ---- Consume registers: ballot-compacted candidate push (no atomics) ----
        uint64_t* myseg = seg[p] + (warp << 6);
        uint32_t base = 0;
        #pragma unroll
        for (int u = 0; u < 8; ++u) {
            const uint32_t eb = (uint32_t)(tid + u * NTHREADS) * 4u;
            unsigned a;
            a = __ballot_sync(0xffffffffu, v[u].x >= THRESH);
            if (v[u].x >= THRESH) { uint32_t o = base + __popc(a & ltm); if (o < WCAP) myseg[o] = make_key(__float_as_uint(v[u].x), eb + 0u); }
            base += (uint32_t)__popc(a);
            a = __ballot_sync(0xffffffffu, v[u].y >= THRESH);
            if (v[u].y >= THRESH) { uint32_t o = base + __popc(a & ltm); if (o < WCAP) myseg[o] = make_key(__float_as_uint(v[u].y), eb + 1u); }
            base += (uint32_t)__popc(a);
            a = __ballot_sync(0xffffffffu, v[u].z >= THRESH);
            if (v[u].z >= THRESH) { uint32_t o = base + __popc(a & ltm); if (o < WCAP) myseg[o] = make_key(__float_as_uint(v[u].z), eb + 2u); }
            base += (uint32_t)__popc(a);
            a = __ballot_sync(0xffffffffu, v[u].w >= THRESH);
            if (v[u].w >= THRESH) { uint32_t o = base + __popc(a & ltm); if (o < WCAP) myseg[o] = make_key(__float_as_uint(v[u].w), eb + 3u); }
            base += (uint32_t)__popc(a);
        }
        if (lane == 0) cnt_s[p][warp] = base;

        // ---- Prefetch next row: async zeros + all 8 loads (overlap rank below) ----
        if (r + 1 < RPB) {
            if (tid == 0) {
                uint32_t zaddr = (uint32_t)__cvta_generic_to_shared(zbuf);
                float* on = out + (row + 1) * (size_t)NN;
                #pragma unroll
                for (int k = 0; k < 8; ++k)
                    asm volatile("cp.async.bulk.global.shared::cta.bulk_group [%0], [%1], %2;"
                                 :: "l"(on + k * 1024), "r"(zaddr), "r"(4096) : "memory");
                asm volatile("cp.async.bulk.commit_group;" ::: "memory");
            }
            const float4* ar = reinterpret_cast<const float4*>(A + (row + 1) * (size_t)NN);
            #pragma unroll
            for (int u = 0; u < 8; ++u) v[u] = ar[tid + u * NTHREADS];
        }
        __syncthreads();   // S1: seg[p]/cnt_s[p] complete

        // ---- Validity: segments within cap, KSEL <= C <= DCAP ----
        uint32_t C = 0; bool ok = true;
        uint32_t off[8];
        #pragma unroll
        for (int w = 0; w < 8; ++w) { off[w] = C; const uint32_t cw = cnt_s[p][w]; C += cw; ok &= (cw <= WCAP); }
        ok = ok && (C >= KSEL) && (C <= DCAP);

        if (ok) {
            // compact into dense dcand[0..C)
            #pragma unroll
            for (int s = tid; s < FCAP; s += NTHREADS) {
                const int w = s >> 6, o = s & (WCAP - 1);
                if ((uint32_t)o < cnt_s[p][w]) dcand[off[w] + o] = seg[p][s];
            }
            if (tid == 0) {   // retire this row's zero-group (keep next row's pending)
                if (r + 1 < RPB) asm volatile("cp.async.bulk.wait_group 1;" ::: "memory");
                else             asm volatile("cp.async.bulk.wait_group 0;" ::: "memory");
            }
            __syncthreads();  // S2: dcand ready, zeros(row) committed

            // exact rank (value desc, index asc); scatter the KSEL winners
            for (uint32_t j = tid; j < C; j += NTHREADS) {
                const uint64_t kj = dcand[j];
                uint32_t rr = 0;
                for (uint32_t m = 0; m < C; ++m)
                    rr += (dcand[m] > kj) ? 1u : 0u;       // uniform: broadcast LDS
                if (rr < KSEL) {
                    const uint32_t idx = 0xFFFFu ^ (uint32_t)(kj & 0xFFFFu);
                    orowf[idx] = __uint_as_float((uint32_t)(kj >> 16));
                }
            }
            continue;   // loop-top barrier (S1 of next iter) protects reuse
        }

        // ============== Exact per-row fallback (~0.5% of rows) ==============
        if (tid == 0) {
            if (r + 1 < RPB) asm volatile("cp.async.bulk.wait_group 1;" ::: "memory");
            else             asm volatile("cp.async.bulk.wait_group 0;" ::: "memory");
        }
        hist[tid] = 0;
        if (tid == 0) { sh_b = 0; sh_kp = 0; sh_deg = 0; fb_count = 0; }
        __syncthreads();

        const float* arowf = A + row * (size_t)NN;
        const float4* arow = reinterpret_cast<const float4*>(arowf);
        for (int i = tid; i < NN / 4; i += NTHREADS) {
            float4 q = arow[i];
            uint32_t b0 = (q.x > 0.0f) ? __float_as_uint(q.x) : 0u;
            uint32_t b1 = (q.y > 0.0f) ? __float_as_uint(q.y) : 0u;
            uint32_t b2 = (q.z > 0.0f) ? __float_as_uint(q.z) : 0u;
            uint32_t b3 = (q.w > 0.0f) ? __float_as_uint(q.w) : 0u;
            hist_add(hist, b0 >> 24, b0 != 0u, lane);
            hist_add(hist, b1 >> 24, b1 != 0u, lane);
            hist_add(hist, b2 >> 24, b2 != 0u, lane);
            hist_add(hist, b3 >> 24, b3 != 0u, lane);
        }
        __syncthreads();

        {   // suffix scan over 256 byte bins
            const uint32_t v0 = hist[tid];
            uint32_t vv = v0;
            #pragma unroll
            for (int d = 1; d < 32; d <<= 1) {
                uint32_t o = __shfl_down_sync(0xffffffffu, vv, d);
                if (lane + d < 32) vv += o;
            }
            if (lane == 0) wsum[tid >> 5] = vv;
            __syncthreads();
            uint32_t hi = 0;
            #pragma unroll
            for (int w = 0; w < 8; ++w) if (w > (tid >> 5)) hi += wsum[w];
            const uint32_t s   = vv + hi;    // count with top byte >= tid
            const uint32_t nxt = s - v0;     // count with top byte  > tid
            if (tid == 0 && s < KSEL) sh_deg = 1;
            if (s >= KSEL && nxt < KSEL) { sh_b = (uint32_t)tid; sh_kp = KSEL - nxt; }
            __syncthreads();
        }
        const uint32_t b   = sh_b;
        const uint32_t kp  = sh_kp;
        const bool     deg = (sh_deg != 0);
        uint64_t* fcand = seg[p];            // reuse this row's segment space

        for (int i = tid; i < NN; i += NTHREADS) {
            const float    q    = arowf[i];
            const uint32_t bits = (q > 0.0f) ? __float_as_uint(q) : 0u;
            if (deg) {
                if (bits) orowf[i] = q;                  // <K positives: keep all
            } else if (bits) {
                const uint32_t byte = bits >> 24;
                if (byte > b) orowf[i] = q;
                else if (byte == b) {
                    const uint32_t pp = atomicAdd(&fb_count, 1u);
                    if (pp < FCAP) fcand[pp] = make_key(bits, (uint32_t)i);
                }
            }
        }
        __syncthreads();

        if (!deg) {
            const uint32_t C2 = fb_count;
            if (C2 <= FCAP) {
                for (uint32_t j = tid; j < C2; j += NTHREADS) {
                    const uint64_t kj = fcand[j];
                    uint32_t rr = 0;
                    for (uint32_t mm = 0; mm < C2; ++mm)
                        rr += (fcand[mm] > kj) ? 1u : 0u;
                    if (rr < kp) {
                        const uint32_t idx = 0xFFFFu ^ (uint32_t)(kj & 0xFFFFu);
                        orowf[idx] = __uint_as_float((uint32_t)(kj >> 16));
                    }
                }
            } else {
                // ultra-rare duplicate-heavy rows: O(N) exact rank per candidate
                for (int i = tid; i < NN; i += NTHREADS) {
                    const float    q    = arowf[i];
                    const uint32_t bits = (q > 0.0f) ? __float_as_uint(q) : 0u;
                    if (bits && (bits >> 24) == b) {
                        const uint64_t kj = make_key(bits, (uint32_t)i);
                        uint32_t rr = 0;
                        for (int j2 = 0; j2 < NN; ++j2) {
                            const float    w  = arowf[j2];
                            const uint32_t wb = (w > 0.0f) ? __float_as_uint(w) : 0u;
                            if (wb && (wb >> 24) == b && make_key(wb, (uint32_t)j2) > kj) ++rr;
                        }
                        if (rr < kp) orowf[i] = q;
                    }
                }
            }
        }
        // loop-top S1 of next iteration orders all reuse
    }
}

extern "C" void kernel_launch(void* const* d_in, const int* in_sizes, int n_in,
                              void* d_out, int out_size) {
    const float* A   = (const float*)d_in[0];
    float*       out = (float*)d_out;
    (void)in_sizes; (void)n_in; (void)out_size;   // idx (d_in[1]) unused by the reference
    topk_mask_kernel<<<NN / RPB, NTHREADS>>>(A, out);
}